// round 9
// baseline (speedup 1.0000x reference)
#include <cuda_runtime.h>
#include <cstdint>

// ---- fixed dims ----
#define RVD 4
#define RD 16
#define F_IN 64
#define F_OUT 64
#define BVD 16               // B*V
#define ROWS_PER_BV 65536    // T*N*D
#define TILE 128             // rows per tile
#define NTILES (ROWS_PER_BV / TILE)   // 512
#define BLOCK 256            // 8 warps: 4 row-groups x 2 col-halves
#define GRIDX 18             // 18*16 = 288 CTAs ~ one wave at 2 CTA/SM

// Per-bv folded factor G2[a][e] = sum_c G1[a][c] * fac_out[c][e], tf32-rounded bits, row-major 64x64
__device__ uint32_t g_G2[BVD * F_IN * F_OUT];

// ---------------- helpers ----------------
__device__ __forceinline__ uint32_t cvt_tf32(float f) {
    uint32_t o;
    asm("cvt.rna.tf32.f32 %0, %1;" : "=r"(o) : "f"(f));
    return o;
}
__device__ __forceinline__ void mma_tf32(float c[4],
                                         uint32_t a0, uint32_t a1, uint32_t a2, uint32_t a3,
                                         uint32_t b0, uint32_t b1) {
    asm volatile(
        "mma.sync.aligned.m16n8k8.row.col.f32.tf32.tf32.f32 "
        "{%0,%1,%2,%3}, {%4,%5,%6,%7}, {%8,%9}, {%0,%1,%2,%3};"
        : "+f"(c[0]), "+f"(c[1]), "+f"(c[2]), "+f"(c[3])
        : "r"(a0), "r"(a1), "r"(a2), "r"(a3), "r"(b0), "r"(b1));
}

// ---------------- prep: G2 = (fac_in^T W) @ fac_out, tf32-rounded ----------------
__global__ void prep_kernel(const int* __restrict__ var_idx,
                            const float* __restrict__ core,
                            const float* __restrict__ factor_vars,
                            const float* __restrict__ fac_in,
                            const float* __restrict__ fac_out) {
    __shared__ float W[RD][RD];
    __shared__ float FO[RD][F_OUT];
    int bv = blockIdx.x;       // 0..15
    int t  = threadIdx.x;      // 0..63 (= 'a')
    int vi = var_idx[bv];

    #pragma unroll
    for (int kk = 0; kk < 4; kk++) {
        int idx = t * 4 + kk;
        int b = idx >> 4, c = idx & 15;
        float s = 0.f;
        #pragma unroll
        for (int A = 0; A < RVD; A++)
            s += factor_vars[vi * RVD + A] * core[(A * RD + b) * RD + c];
        W[b][c] = s;
    }
    for (int i = t; i < RD * F_OUT; i += 64)
        FO[i >> 6][i & 63] = fac_out[i];
    __syncthreads();

    float fin[RD];
    #pragma unroll
    for (int b = 0; b < RD; b++) fin[b] = fac_in[b * F_IN + t];
    float g1r[RD];
    #pragma unroll
    for (int c = 0; c < RD; c++) {
        float s = 0.f;
        #pragma unroll
        for (int b = 0; b < RD; b++) s += fin[b] * W[b][c];
        g1r[c] = s;
    }
    for (int e = 0; e < F_OUT; e++) {
        float s = 0.f;
        #pragma unroll
        for (int c = 0; c < RD; c++) s += g1r[c] * FO[c][e];
        g_G2[bv * (F_IN * F_OUT) + t * F_OUT + e] = cvt_tf32(s);
    }
}

// ---------------- main: warp-MMA tf32, no smem, no block syncs in loop ----------------
__global__ __launch_bounds__(BLOCK, 2)
void tucker_hmma(const float* __restrict__ x, float* __restrict__ out) {
    const int tid = threadIdx.x;
    const int lid = tid & 31;
    const int wid = tid >> 5;          // 0..7
    const int h   = wid & 1;           // column half (0: e 0..31, 1: e 32..63)
    const int rg  = wid >> 1;          // row group 0..3 -> rows rg*32 .. rg*32+31
    const int gid = lid >> 2;          // 0..7
    const int tig = lid & 3;           // 0..3
    const int bv  = blockIdx.y;
    const int cb  = h * 32;

    // ---- B fragments for all K=64, held in registers for the whole kernel ----
    // b0[k][nt]: (krow = k*8+tig,   ncol = cb + nt*8 + gid)
    // b1[k][nt]: (krow = k*8+tig+4, ncol = cb + nt*8 + gid)
    uint32_t b0[8][4], b1[8][4];
    {
        const uint32_t* G2 = g_G2 + bv * (F_IN * F_OUT);
        #pragma unroll
        for (int k = 0; k < 8; k++) {
            #pragma unroll
            for (int nt = 0; nt < 4; nt++) {
                int n = cb + nt * 8 + gid;
                b0[k][nt] = G2[(k * 8 + tig) * F_OUT + n];
                b1[k][nt] = G2[(k * 8 + tig + 4) * F_OUT + n];
            }
        }
    }

    const size_t bvbase = (size_t)bv * ROWS_PER_BV * 64;

    for (int t = blockIdx.x; t < NTILES; t += GRIDX) {
        const size_t toff = bvbase + (size_t)t * (TILE * 64);

        #pragma unroll
        for (int mt = 0; mt < 2; mt++) {
            const int row0 = rg * 32 + mt * 16 + gid;      // this thread's upper A row
            const float* xa = x + toff + (size_t)row0 * 64 + tig;

            float acc[4][4];
            #pragma unroll
            for (int nt = 0; nt < 4; nt++)
                #pragma unroll
                for (int i = 0; i < 4; i++) acc[nt][i] = 0.f;

            // two K-halves of 4 k-steps each: 16 loads -> 16 cvt -> 16 mma
            #pragma unroll
            for (int half = 0; half < 2; half++) {
                float fa0[4], fa1[4], fa2[4], fa3[4];
                #pragma unroll
                for (int kk = 0; kk < 4; kk++) {
                    int kc = (half * 4 + kk) * 8;
                    fa0[kk] = xa[kc];              // (row0,   col kc+tig)
                    fa2[kk] = xa[kc + 4];          // (row0,   col kc+tig+4)
                    fa1[kk] = xa[512 + kc];        // (row0+8, col kc+tig)
                    fa3[kk] = xa[512 + kc + 4];    // (row0+8, col kc+tig+4)
                }
                uint32_t a0[4], a1[4], a2[4], a3[4];
                #pragma unroll
                for (int kk = 0; kk < 4; kk++) {
                    a0[kk] = cvt_tf32(fa0[kk]);
                    a1[kk] = cvt_tf32(fa1[kk]);
                    a2[kk] = cvt_tf32(fa2[kk]);
                    a3[kk] = cvt_tf32(fa3[kk]);
                }
                #pragma unroll
                for (int kk = 0; kk < 4; kk++) {
                    int k = half * 4 + kk;
                    #pragma unroll
                    for (int nt = 0; nt < 4; nt++)
                        mma_tf32(acc[nt], a0[kk], a1[kk], a2[kk], a3[kk],
                                 b0[k][nt], b1[k][nt]);
                }
            }

            // ---- store C fragments: (row0, col cb+nt*8+tig*2) and (row0+8, same) ----
            float2* o2 = reinterpret_cast<float2*>(out + toff);
            const int obase = row0 * 32 + (cb >> 1) + tig;
            #pragma unroll
            for (int nt = 0; nt < 4; nt++) {
                o2[obase + nt * 4]       = make_float2(acc[nt][0], acc[nt][1]);
                o2[obase + 256 + nt * 4] = make_float2(acc[nt][2], acc[nt][3]);  // row0+8 -> +8*32
            }
        }
    }
}

extern "C" void kernel_launch(void* const* d_in, const int* in_sizes, int n_in,
                              void* d_out, int out_size) {
    const float* x           = (const float*)d_in[0];
    const int*   var_idx     = (const int*)d_in[1];
    const float* core        = (const float*)d_in[2];
    const float* factor_vars = (const float*)d_in[3];
    const float* fac_in      = (const float*)d_in[4];
    const float* fac_out     = (const float*)d_in[5];
    float* out = (float*)d_out;

    prep_kernel<<<BVD, 64>>>(var_idx, core, factor_vars, fac_in, fac_out);

    dim3 grid(GRIDX, BVD);
    tucker_hmma<<<grid, BLOCK>>>(x, out);
}